// round 16
// baseline (speedup 1.0000x reference)
#include <cuda_runtime.h>
#include <cuda_bf16.h>
#include <cstdint>

#define B_   8
#define N_   207
#define T_   12
#define C_   64
#define L_   2484
#define LPAD 2496
#define NT2  20          // 20 tiles of 128 keys
#define QT   52          // 52 tiles of 48 query rows
#define LOG2E 1.4426950408889634f

// ---------------- scratch (module globals) ----------------
__device__ float g_h[B_ * LPAD * C_];            // [b][l][c] fp32 (residual)
__device__ __nv_bfloat16 g_qb[B_ * LPAD * 8];    // [b][l][d]  (q pre-scaled by log2e)
__device__ __nv_bfloat16 g_kb[B_ * LPAD * 8];    // [b][m][d]
__device__ __nv_bfloat16 g_vb[B_ * 64 * LPAD];   // [b][c][m] transposed, keys PAIR-PERMUTED

// fragment-packed weights: [ks][ntile][lane][2]
__device__ float g_fwAhi[12288], g_fwAlo[12288];
__device__ float g_fwBhi[12288], g_fwBlo[12288];
__device__ float g_fwv[4096];
__device__ float g_fwq[512], g_fwk[512];         // wq scaled by log2e

__device__ __forceinline__ float to_tf32(float x) {
    unsigned r;
    asm("cvt.rna.tf32.f32 %0, %1;" : "=r"(r) : "f"(x));
    return __uint_as_float(r);
}

__device__ __forceinline__ float ex2(float x) {
    float r;
    asm("ex2.approx.f32 %0, %1;" : "=f"(r) : "f"(x));
    return r;
}

__device__ __forceinline__ unsigned pack_bf16(float lo, float hi) {
    unsigned r;
    asm("cvt.rn.bf16x2.f32 %0, %1, %2;" : "=r"(r) : "f"(hi), "f"(lo));
    return r;
}

__device__ __forceinline__ void mma_tf32(float* d,
                                         unsigned a0, unsigned a1, unsigned a2, unsigned a3,
                                         unsigned b0, unsigned b1) {
    asm("mma.sync.aligned.m16n8k8.row.col.f32.tf32.tf32.f32 "
        "{%0,%1,%2,%3},{%4,%5,%6,%7},{%8,%9},{%0,%1,%2,%3};"
        : "+f"(d[0]), "+f"(d[1]), "+f"(d[2]), "+f"(d[3])
        : "r"(a0), "r"(a1), "r"(a2), "r"(a3), "r"(b0), "r"(b1));
}

__device__ __forceinline__ void mma_bf16_k8(float* d, unsigned a0, unsigned a1, unsigned b0) {
    asm("mma.sync.aligned.m16n8k8.row.col.f32.bf16.bf16.f32 "
        "{%0,%1,%2,%3},{%4,%5},{%6},{%0,%1,%2,%3};"
        : "+f"(d[0]), "+f"(d[1]), "+f"(d[2]), "+f"(d[3])
        : "r"(a0), "r"(a1), "r"(b0));
}
__device__ __forceinline__ void mma_bf16_k16(float* d,
                                             unsigned a0, unsigned a1, unsigned a2, unsigned a3,
                                             unsigned b0, unsigned b1) {
    asm("mma.sync.aligned.m16n8k16.row.col.f32.bf16.bf16.f32 "
        "{%0,%1,%2,%3},{%4,%5,%6,%7},{%8,%9},{%0,%1,%2,%3};"
        : "+f"(d[0]), "+f"(d[1]), "+f"(d[2]), "+f"(d[3])
        : "r"(a0), "r"(a1), "r"(a2), "r"(a3), "r"(b0), "r"(b1));
}

__device__ __forceinline__ void cp16(unsigned int saddr, const void* gaddr) {
    asm volatile("cp.async.ca.shared.global [%0], [%1], 16;" :: "r"(saddr), "l"(gaddr));
}
__device__ __forceinline__ void cp_commit() {
    asm volatile("cp.async.commit_group;" ::: "memory");
}
__device__ __forceinline__ void cp_wait0() {
    asm volatile("cp.async.wait_group 0;" ::: "memory");
}

// ---------------------------------------------------------------------------
// Kernel 0: pack weights into mma-fragment order (wq scaled by log2e)
// ---------------------------------------------------------------------------
__global__ void k0_pack(const float* __restrict__ wA, const float* __restrict__ wB,
                        const float* __restrict__ wq, const float* __restrict__ wk,
                        const float* __restrict__ wv)
{
    int t = blockIdx.x * 256 + threadIdx.x;
    if (t < 12288) {
        int ks = t >> 9, r = t & 511;
        int ntg = r >> 6, q = r & 63;
        int lane = q >> 1, e = q & 1;
        int gid = lane >> 2, tq = lane & 3;
        int n = ntg * 8 + gid;
        int k = ks * 8 + tq + 4 * e;
        float a = wA[n * 192 + k], bw = wB[n * 192 + k];
        float ahi = to_tf32(a), bhi = to_tf32(bw);
        int off = ((ks * 8 + ntg) * 32 + lane) * 2 + e;
        g_fwAhi[off] = ahi; g_fwAlo[off] = to_tf32(a - ahi);
        g_fwBhi[off] = bhi; g_fwBlo[off] = to_tf32(bw - bhi);
    }
    if (t < 4096) {
        int ks = t >> 9, r = t & 511;
        int ntg = r >> 6, q = r & 63;
        int lane = q >> 1, e = q & 1;
        int gid = lane >> 2, tq = lane & 3;
        g_fwv[((ks * 8 + ntg) * 32 + lane) * 2 + e] = wv[(ntg * 8 + gid) * 64 + ks * 8 + tq + 4 * e];
    }
    if (t < 512) {
        int ks = t >> 6, q = t & 63;
        int lane = q >> 1, e = q & 1;
        int gid = lane >> 2, tq = lane & 3;
        int k = ks * 8 + tq + 4 * e;
        g_fwq[(ks * 32 + lane) * 2 + e] = wq[gid * 64 + k] * LOG2E;
        g_fwk[(ks * 32 + lane) * 2 + e] = wk[gid * 64 + k];
    }
}

// ---------------------------------------------------------------------------
// Kernel 1: conv(x2, 3xTF32 mma) + GLU gate + v/q/k projections
// grid (QT, B): 48-row tiles, 192 threads (6 warps: mw=wid>>1, nw=wid&1)
// ---------------------------------------------------------------------------
__global__ void __launch_bounds__(192, 3)
k1_conv_qkv(const float* __restrict__ X,
            const float* __restrict__ bA, const float* __restrict__ bB,
            const float* __restrict__ bq, const float* __restrict__ bk,
            const float* __restrict__ bv)
{
    extern __shared__ float sm1[];
    float* xs = sm1;            // [l][pitch 196]
    float* hs = sm1 + 9408;     // [l][pitch 68]

    const int tid  = threadIdx.x;
    const int wid  = tid >> 5;
    const int lane = tid & 31;
    const int gid  = lane >> 2;
    const int tq   = lane & 3;
    const int mw   = wid >> 1;
    const int nw   = wid & 1;
    const int m0   = mw * 16;
    const int nbase = nw * 32;
    const int b    = blockIdx.y;
    const int l0   = blockIdx.x * 48;

    for (int e = tid; e < 48 * 192; e += 192) {
        int l = e / 192, r = e - l * 192;
        int ci = r / 3, k = r - ci * 3;
        int gl = l0 + l;
        float v = 0.f;
        if (gl < L_) {
            int n = gl / 12, t = gl - n * 12;
            int tt = t - 2 + k;
            if (tt >= 0) v = X[((b * N_ + n) * T_ + tt) * C_ + ci];
        }
        xs[l * 196 + r] = v;
    }
    __syncthreads();

    float accA[4][4], accB[4][4];
    #pragma unroll
    for (int i = 0; i < 4; i++)
        #pragma unroll
        for (int j = 0; j < 4; j++) { accA[i][j] = 0.f; accB[i][j] = 0.f; }

    #pragma unroll 4
    for (int ks = 0; ks < 24; ks++) {
        const int k0 = ks * 8;
        float f0 = xs[(m0 + gid) * 196 + k0 + tq];
        float f1 = xs[(m0 + gid + 8) * 196 + k0 + tq];
        float f2 = xs[(m0 + gid) * 196 + k0 + tq + 4];
        float f3 = xs[(m0 + gid + 8) * 196 + k0 + tq + 4];
        float h0 = to_tf32(f0), h1 = to_tf32(f1), h2 = to_tf32(f2), h3 = to_tf32(f3);
        unsigned ah0 = __float_as_uint(h0), ah1 = __float_as_uint(h1);
        unsigned ah2 = __float_as_uint(h2), ah3 = __float_as_uint(h3);
        unsigned al0 = __float_as_uint(to_tf32(f0 - h0));
        unsigned al1 = __float_as_uint(to_tf32(f1 - h1));
        unsigned al2 = __float_as_uint(to_tf32(f2 - h2));
        unsigned al3 = __float_as_uint(to_tf32(f3 - h3));
        #pragma unroll
        for (int nt = 0; nt < 4; nt++) {
            const int off = ((ks * 8 + (nbase >> 3) + nt) * 32 + lane) * 2;
            float2 whA = __ldg((const float2*)&g_fwAhi[off]);
            float2 wlA = __ldg((const float2*)&g_fwAlo[off]);
            float2 whB = __ldg((const float2*)&g_fwBhi[off]);
            float2 wlB = __ldg((const float2*)&g_fwBlo[off]);
            unsigned bhA0 = __float_as_uint(whA.x), bhA1 = __float_as_uint(whA.y);
            unsigned blA0 = __float_as_uint(wlA.x), blA1 = __float_as_uint(wlA.y);
            unsigned bhB0 = __float_as_uint(whB.x), bhB1 = __float_as_uint(whB.y);
            unsigned blB0 = __float_as_uint(wlB.x), blB1 = __float_as_uint(wlB.y);
            mma_tf32(accA[nt], ah0, ah1, ah2, ah3, bhA0, bhA1);
            mma_tf32(accA[nt], ah0, ah1, ah2, ah3, blA0, blA1);
            mma_tf32(accA[nt], al0, al1, al2, al3, bhA0, bhA1);
            mma_tf32(accB[nt], ah0, ah1, ah2, ah3, bhB0, bhB1);
            mma_tf32(accB[nt], ah0, ah1, ah2, ah3, blB0, blB1);
            mma_tf32(accB[nt], al0, al1, al2, al3, bhB0, bhB1);
        }
    }

    {
        const int rlo = m0 + gid, rhi = rlo + 8;
        const int gl_lo = l0 + rlo, gl_hi = l0 + rhi;
        #pragma unroll
        for (int nt = 0; nt < 4; nt++) {
            const int col = nbase + nt * 8 + 2 * tq;
            float ba0 = __ldg(bA + col), ba1 = __ldg(bA + col + 1);
            float bb0 = __ldg(bB + col), bb1 = __ldg(bB + col + 1);
            float h00 = (accA[nt][0] + ba0) / (1.f + __expf(-(accB[nt][0] + bb0)));
            float h01 = (accA[nt][1] + ba1) / (1.f + __expf(-(accB[nt][1] + bb1)));
            float h10 = (accA[nt][2] + ba0) / (1.f + __expf(-(accB[nt][2] + bb0)));
            float h11 = (accA[nt][3] + ba1) / (1.f + __expf(-(accB[nt][3] + bb1)));
            *(float2*)&hs[rlo * 68 + col] = make_float2(h00, h01);
            *(float2*)&hs[rhi * 68 + col] = make_float2(h10, h11);
            if (gl_lo < L_) *(float2*)&g_h[((size_t)b * LPAD + gl_lo) * 64 + col] = make_float2(h00, h01);
            if (gl_hi < L_) *(float2*)&g_h[((size_t)b * LPAD + gl_hi) * 64 + col] = make_float2(h10, h11);
        }
    }
    __syncthreads();

    // ---- v = h @ wv^T + bv, stored PAIR-PERMUTED bf16 ----
    {
        float accV[4][4];
        #pragma unroll
        for (int i = 0; i < 4; i++)
            #pragma unroll
            for (int j = 0; j < 4; j++) accV[i][j] = 0.f;

        #pragma unroll
        for (int ks = 0; ks < 8; ks++) {
            const int k0 = ks * 8;
            unsigned a0 = __float_as_uint(hs[(m0 + gid) * 68 + k0 + tq]);
            unsigned a1 = __float_as_uint(hs[(m0 + gid + 8) * 68 + k0 + tq]);
            unsigned a2 = __float_as_uint(hs[(m0 + gid) * 68 + k0 + tq + 4]);
            unsigned a3 = __float_as_uint(hs[(m0 + gid + 8) * 68 + k0 + tq + 4]);
            #pragma unroll
            for (int nt = 0; nt < 4; nt++) {
                const int off = ((ks * 8 + (nbase >> 3) + nt) * 32 + lane) * 2;
                float2 w = __ldg((const float2*)&g_fwv[off]);
                mma_tf32(accV[nt], a0, a1, a2, a3,
                         __float_as_uint(w.x), __float_as_uint(w.y));
            }
        }

        const int gb = l0 + m0;
        const int pos_lo = gb + ((gid >> 1) << 2) + (gid & 1);
        const int pos_hi = pos_lo + 2;
        #pragma unroll
        for (int nt = 0; nt < 4; nt++) {
            const int col = nbase + nt * 8 + 2 * tq;
            float bv0 = __ldg(bv + col), bv1 = __ldg(bv + col + 1);
            g_vb[((size_t)(b * 64 + col))     * LPAD + pos_lo] = __float2bfloat16(accV[nt][0] + bv0);
            g_vb[((size_t)(b * 64 + col + 1)) * LPAD + pos_lo] = __float2bfloat16(accV[nt][1] + bv1);
            g_vb[((size_t)(b * 64 + col))     * LPAD + pos_hi] = __float2bfloat16(accV[nt][2] + bv0);
            g_vb[((size_t)(b * 64 + col + 1)) * LPAD + pos_hi] = __float2bfloat16(accV[nt][3] + bv1);
        }
    }

    // ---- q,k projections (nw==0 warps); q in log2e-scaled domain ----
    if (nw == 0) {
        float accQ[4] = {0.f, 0.f, 0.f, 0.f};
        float accK[4] = {0.f, 0.f, 0.f, 0.f};

        #pragma unroll
        for (int ks = 0; ks < 8; ks++) {
            const int k0 = ks * 8;
            unsigned a0 = __float_as_uint(hs[(m0 + gid) * 68 + k0 + tq]);
            unsigned a1 = __float_as_uint(hs[(m0 + gid + 8) * 68 + k0 + tq]);
            unsigned a2 = __float_as_uint(hs[(m0 + gid) * 68 + k0 + tq + 4]);
            unsigned a3 = __float_as_uint(hs[(m0 + gid + 8) * 68 + k0 + tq + 4]);
            float2 wqf = __ldg((const float2*)&g_fwq[(ks * 32 + lane) * 2]);
            float2 wkf = __ldg((const float2*)&g_fwk[(ks * 32 + lane) * 2]);
            mma_tf32(accQ, a0, a1, a2, a3, __float_as_uint(wqf.x), __float_as_uint(wqf.y));
            mma_tf32(accK, a0, a1, a2, a3, __float_as_uint(wkf.x), __float_as_uint(wkf.y));
        }

        const int gl_lo = l0 + m0 + gid, gl_hi = gl_lo + 8;
        float bq0 = __ldg(bq + 2 * tq) * LOG2E, bq1 = __ldg(bq + 2 * tq + 1) * LOG2E;
        float bk0 = __ldg(bk + 2 * tq), bk1 = __ldg(bk + 2 * tq + 1);
        char* qbase = (char*)g_qb + ((size_t)b * LPAD) * 16;
        char* kbase = (char*)g_kb + ((size_t)b * LPAD) * 16;
        *(unsigned*)(qbase + (size_t)gl_lo * 16 + tq * 4) = pack_bf16(accQ[0] + bq0, accQ[1] + bq1);
        *(unsigned*)(qbase + (size_t)gl_hi * 16 + tq * 4) = pack_bf16(accQ[2] + bq0, accQ[3] + bq1);
        *(unsigned*)(kbase + (size_t)gl_lo * 16 + tq * 4) = pack_bf16(accK[0] + bk0, accK[1] + bk1);
        *(unsigned*)(kbase + (size_t)gl_hi * 16 + tq * 4) = pack_bf16(accK[2] + bk0, accK[3] + bk1);
    }
}

// ---------------------------------------------------------------------------
// Kernel 2: flash attention, 128-key mega-tiles, log2-domain softmax,
// bf16 mma, P in registers, ones-channel denominator.
// oS ALIASES vS0 (combine phase starts after all V reads; sync separates).
// smem words: vS0[72*72] 0..5183 | vS1 5184..10367 | kS[2][128*4] 10368..11391
//             mxS[2*48] 11392 | ssS[2*48] 11488   -> total 11584 (~46.3KB, 4/SM)
// ---------------------------------------------------------------------------
__global__ void __launch_bounds__(192, 4)
k2_attn(const float* __restrict__ gamma, float* __restrict__ out)
{
    extern __shared__ float sm[];
    float* vS0 = sm;                  // [72 ch][72 words], data words 0..63
    float* vS1 = sm + 5184;
    float* kS0 = sm + 10368;          // 128 keys x 16B
    float* kS1 = sm + 10880;
    float* mxS = sm + 11392;          // [nw][48]
    float* ssS = sm + 11488;          // [nw][48]
    float* oS  = sm;                  // [48][66] ALIASES vS0 (post-loop only)

    const int tid  = threadIdx.x;
    const int wid  = tid >> 5;
    const int lane = tid & 31;
    const int gid  = lane >> 2;
    const int tq   = lane & 3;
    const int mw   = wid >> 1;        // 0..2
    const int nw   = wid & 1;         // 0..1
    const int m0   = mw * 16;
    const int kb   = nw * 32;
    const int b    = blockIdx.y;
    const int l0   = blockIdx.x * 48;

    const float* kS[2] = {kS0, kS1};
    const float* vS[2] = {vS0, vS1};

    unsigned kBase[2], vBase[2];
    kBase[0] = (unsigned)__cvta_generic_to_shared(kS0);
    kBase[1] = (unsigned)__cvta_generic_to_shared(kS1);
    vBase[0] = (unsigned)__cvta_generic_to_shared(vS0);
    vBase[1] = (unsigned)__cvta_generic_to_shared(vS1);

    // ---- init constant rows 64..71 of both v buffers (row 64 = bf16 ones) ----
    for (int e = tid; e < 1152; e += 192) {
        int bufi = e / 576, r = (e % 576) / 72, w = e % 72;
        float* dst = (bufi ? vS1 : vS0) + (64 + r) * 72 + w;
        *(unsigned*)dst = (r == 0) ? 0x3F803F80u : 0u;
    }

    // ---- prologue: tile 0 (128 keys) -> buf 0 ----
    {
        const char* kg = (const char*)g_kb + ((size_t)b * LPAD) * 16;
        if (tid < 128) cp16(kBase[0] + tid * 16, kg + tid * 16);
        const char* vg = (const char*)g_vb + ((size_t)b * 64 * LPAD) * 2;
        #pragma unroll
        for (int u = 0; u < 6; u++) {
            int e = tid + u * 192;
            if (e < 1024) {
                int row = e >> 4, cc = e & 15;
                cp16(vBase[0] + row * 288 + cc * 16, vg + (size_t)row * (LPAD * 2) + cc * 16);
            }
        }
        cp_commit();
    }

    unsigned qa0, qa1;
    {
        const char* qrow = (const char*)g_qb + ((size_t)b * LPAD + l0 + m0) * 16;
        qa0 = *(const unsigned*)(qrow + gid * 16 + 4 * tq);
        qa1 = *(const unsigned*)(qrow + (gid + 8) * 16 + 4 * tq);
    }

    float acc[9][4];                  // tiles 0..7 = channels, tile 8 = denominator
    #pragma unroll
    for (int i = 0; i < 9; i++)
        #pragma unroll
        for (int j = 0; j < 4; j++) acc[i][j] = 0.f;

    float mxlo = -1e30f, mxhi = -1e30f;

    int buf = 0;
    for (int it = 0; it < NT2; it++, buf ^= 1) {
        cp_wait0();
        __syncthreads();

        const char* kC = (const char*)kS[buf];
        const char* vC = (const char*)vS[buf];

        #pragma unroll
        for (int h = 0; h < 2; h++) {
            const int mvalid = L_ - it * 128 - h * 64;

            // ---- QK^T for this half ----
            float s[4][4];
            #pragma unroll
            for (int nt = 0; nt < 4; nt++) {
                s[nt][0] = s[nt][1] = s[nt][2] = s[nt][3] = 0.f;
                unsigned bb = *(const unsigned*)(kC + (h * 64 + kb + nt * 8 + gid) * 16 + 4 * tq);
                mma_bf16_k8(s[nt], qa0, qa1, bb);
            }

            // ---- prefetch next mega-tile (once, from half 0) ----
            if (h == 0 && it + 1 < NT2) {
                const size_t mnext = (size_t)(it + 1) * 128;
                const char* kg = (const char*)g_kb + ((size_t)b * LPAD + mnext) * 16;
                const char* vg = (const char*)g_vb + ((size_t)b * 64 * LPAD + mnext) * 2;
                int nb = buf ^ 1;
                if (tid < 128) cp16(kBase[nb] + tid * 16, kg + tid * 16);
                #pragma unroll
                for (int u = 0; u < 6; u++) {
                    int e = tid + u * 192;
                    if (e < 1024) {
                        int row = e >> 4, cc = e & 15;
                        cp16(vBase[nb] + row * 288 + cc * 16, vg + (size_t)row * (LPAD * 2) + cc * 16);
                    }
                }
                cp_commit();
            }

            // ---- mask ----
            if (mvalid < 64) {
                #pragma unroll
                for (int nt = 0; nt < 4; nt++) {
                    int c0 = kb + nt * 8 + 2 * tq;
                    if (c0 >= mvalid)     { s[nt][0] = -1e30f; s[nt][2] = -1e30f; }
                    if (c0 + 1 >= mvalid) { s[nt][1] = -1e30f; s[nt][3] = -1e30f; }
                }
            }

            // ---- warp-local row max / rescale (log2 domain) ----
            float rlo = fmaxf(fmaxf(s[0][0], s[0][1]), fmaxf(s[1][0], s[1][1]));
            rlo = fmaxf(rlo, fmaxf(fmaxf(s[2][0], s[2][1]), fmaxf(s[3][0], s[3][1])));
            float rhi = fmaxf(fmaxf(s[0][2], s[0][3]), fmaxf(s[1][2], s[1][3]));
            rhi = fmaxf(rhi, fmaxf(fmaxf(s[2][2], s[2][3]), fmaxf(s[3][2], s[3][3])));
            rlo = fmaxf(rlo, __shfl_xor_sync(0xffffffff, rlo, 1));
            rlo = fmaxf(rlo, __shfl_xor_sync(0xffffffff, rlo, 2));
            rhi = fmaxf(rhi, __shfl_xor_sync(0xffffffff, rhi, 1));
            rhi = fmaxf(rhi, __shfl_xor_sync(0xffffffff, rhi, 2));
            float nmxlo = fmaxf(mxlo, rlo);
            float nmxhi = fmaxf(mxhi, rhi);
            float corrlo = ex2(mxlo - nmxlo);
            float corrhi = ex2(mxhi - nmxhi);
            mxlo = nmxlo; mxhi = nmxhi;

            // ---- exp2 in place ----
            #pragma unroll
            for (int nt = 0; nt < 4; nt++) {
                s[nt][0] = ex2(s[nt][0] - mxlo);
                s[nt][1] = ex2(s[nt][1] - mxlo);
                s[nt][2] = ex2(s[nt][2] - mxhi);
                s[nt][3] = ex2(s[nt][3] - mxhi);
            }

            // ---- pack P into bf16 A-fragments ----
            unsigned pa[2][4];
            pa[0][0] = pack_bf16(s[0][0], s[0][1]);
            pa[0][1] = pack_bf16(s[0][2], s[0][3]);
            pa[0][2] = pack_bf16(s[1][0], s[1][1]);
            pa[0][3] = pack_bf16(s[1][2], s[1][3]);
            pa[1][0] = pack_bf16(s[2][0], s[2][1]);
            pa[1][1] = pack_bf16(s[2][2], s[2][3]);
            pa[1][2] = pack_bf16(s[3][0], s[3][1]);
            pa[1][3] = pack_bf16(s[3][2], s[3][3]);

            // ---- rescale accumulators (skip when no row max moved) ----
            if (!__all_sync(0xffffffffu, (corrlo == 1.f) & (corrhi == 1.f))) {
                #pragma unroll
                for (int nt = 0; nt < 9; nt++) {
                    acc[nt][0] *= corrlo; acc[nt][1] *= corrlo;
                    acc[nt][2] *= corrhi; acc[nt][3] *= corrhi;
                }
            }

            // ---- P@V (+ones channel): 2 k16 steps x 9 tiles, LDS.64 paired V ----
            #pragma unroll
            for (int ks = 0; ks < 2; ks++) {
                const int basew = h * 32 + (kb >> 1) + ks * 8;
                #pragma unroll
                for (int nt = 0; nt < 9; nt++) {
                    uint2 bb = *(const uint2*)(vC + (nt * 8 + gid) * 288 + (basew + 2 * tq) * 4);
                    mma_bf16_k16(acc[nt], pa[ks][0], pa[ks][1], pa[ks][2], pa[ks][3], bb.x, bb.y);
                }
            }
        }
    }

    // ---- split-softmax combine (log2 domain) ----
    if (tq == 0) {
        mxS[nw * 48 + m0 + gid]     = mxlo;
        mxS[nw * 48 + m0 + gid + 8] = mxhi;
        ssS[nw * 48 + m0 + gid]     = acc[8][0];
        ssS[nw * 48 + m0 + gid + 8] = acc[8][2];
    }
    __syncthreads();   // all V reads done; oS may now reuse vS0 space

    const int rlo_i = m0 + gid, rhi_i = m0 + gid + 8;
    float Mlo = fmaxf(mxS[rlo_i], mxS[48 + rlo_i]);
    float Mhi = fmaxf(mxS[rhi_i], mxS[48 + rhi_i]);
    float denlo = ssS[rlo_i] * ex2(mxS[rlo_i] - Mlo) + ssS[48 + rlo_i] * ex2(mxS[48 + rlo_i] - Mlo);
    float denhi = ssS[rhi_i] * ex2(mxS[rhi_i] - Mhi) + ssS[48 + rhi_i] * ex2(mxS[48 + rhi_i] - Mhi);
    float sclo = ex2(mxlo - Mlo) / denlo;
    float schi = ex2(mxhi - Mhi) / denhi;

    if (nw == 0) {
        #pragma unroll
        for (int nt = 0; nt < 8; nt++) {
            const int col = nt * 8 + 2 * tq;
            oS[rlo_i * 66 + col]     = acc[nt][0] * sclo;
            oS[rlo_i * 66 + col + 1] = acc[nt][1] * sclo;
            oS[rhi_i * 66 + col]     = acc[nt][2] * schi;
            oS[rhi_i * 66 + col + 1] = acc[nt][3] * schi;
        }
    }
    __syncthreads();

    if (nw == 1) {
        const float g = gamma[0];
        const int gl_lo = l0 + rlo_i;
        const int gl_hi = l0 + rhi_i;
        #pragma unroll
        for (int nt = 0; nt < 8; nt++) {
            const int col = nt * 8 + 2 * tq;
            if (gl_lo < L_) {
                float2 h2 = *(const float2*)&g_h[((size_t)b * LPAD + gl_lo) * 64 + col];
                float2 o;
                o.x = g * (oS[rlo_i * 66 + col]     + acc[nt][0] * sclo) + h2.x;
                o.y = g * (oS[rlo_i * 66 + col + 1] + acc[nt][1] * sclo) + h2.y;
                *(float2*)&out[((size_t)b * L_ + gl_lo) * 64 + col] = o;
            }
            if (gl_hi < L_) {
                float2 h2 = *(const float2*)&g_h[((size_t)b * LPAD + gl_hi) * 64 + col];
                float2 o;
                o.x = g * (oS[rhi_i * 66 + col]     + acc[nt][2] * schi) + h2.x;
                o.y = g * (oS[rhi_i * 66 + col + 1] + acc[nt][3] * schi) + h2.y;
                *(float2*)&out[((size_t)b * L_ + gl_hi) * 64 + col] = o;
            }
        }
    }
}

// ---------------------------------------------------------------------------
extern "C" void kernel_launch(void* const* d_in, const int* in_sizes, int n_in,
                              void* d_out, int out_size)
{
    const float* X     = (const float*)d_in[0];
    const float* wA    = (const float*)d_in[1];
    const float* bA    = (const float*)d_in[2];
    const float* wB    = (const float*)d_in[3];
    const float* bB    = (const float*)d_in[4];
    const float* wq    = (const float*)d_in[5];
    const float* bq    = (const float*)d_in[6];
    const float* wk    = (const float*)d_in[7];
    const float* bk    = (const float*)d_in[8];
    const float* wv    = (const float*)d_in[9];
    const float* bv    = (const float*)d_in[10];
    const float* gamma = (const float*)d_in[11];
    float* out = (float*)d_out;

    const size_t smem1 = 12672 * sizeof(float);   // ~50.7KB
    cudaFuncSetAttribute(k1_conv_qkv, cudaFuncAttributeMaxDynamicSharedMemorySize, (int)smem1);
    const size_t smem2 = 11584 * sizeof(float);   // ~46.3KB -> 4 blocks/SM
    cudaFuncSetAttribute(k2_attn, cudaFuncAttributeMaxDynamicSharedMemorySize, (int)smem2);

    dim3 grid(QT, B_);
    k0_pack<<<48, 256>>>(wA, wB, wq, wk, wv);
    k1_conv_qkv<<<grid, 192, smem1>>>(X, bA, bB, bq, bk, bv);
    k2_attn<<<grid, 192, smem2>>>(gamma, out);
}

// round 17
// speedup vs baseline: 1.0371x; 1.0371x over previous
#include <cuda_runtime.h>
#include <cuda_bf16.h>
#include <cstdint>

#define B_   8
#define N_   207
#define T_   12
#define C_   64
#define L_   2484
#define LPAD 2496
#define NT2  20          // 20 tiles of 128 keys
#define QT   52          // 52 tiles of 48 query rows
#define LOG2E 1.4426950408889634f

// ---------------- scratch (module globals) ----------------
__device__ float g_h[B_ * LPAD * C_];            // [b][l][c] fp32 (residual)
__device__ __nv_bfloat16 g_qb[B_ * LPAD * 8];    // [b][l][d]  (q pre-scaled by log2e)
__device__ __nv_bfloat16 g_kb[B_ * LPAD * 8];    // [b][m][d]
__device__ __nv_bfloat16 g_vb[B_ * 64 * LPAD];   // [b][c][m] transposed, keys PAIR-PERMUTED

// conv weights: duplicated bf16x2 pairs, fragment order [grp][ntile][lane][2]
__device__ unsigned g_cwAh[12288], g_cwAl[12288];
__device__ unsigned g_cwBh[12288], g_cwBl[12288];
// projection weights (fragment-packed fp32, used as tf32)
__device__ float g_fwv[4096];
__device__ float g_fwq[512], g_fwk[512];         // wq scaled by log2e

__device__ __forceinline__ float to_tf32(float x) {
    unsigned r;
    asm("cvt.rna.tf32.f32 %0, %1;" : "=r"(r) : "f"(x));
    return __uint_as_float(r);
}

__device__ __forceinline__ float ex2(float x) {
    float r;
    asm("ex2.approx.f32 %0, %1;" : "=f"(r) : "f"(x));
    return r;
}

__device__ __forceinline__ unsigned pack_bf16(float lo, float hi) {
    unsigned r;
    asm("cvt.rn.bf16x2.f32 %0, %1, %2;" : "=r"(r) : "f"(hi), "f"(lo));
    return r;
}

__device__ __forceinline__ void mma_tf32(float* d,
                                         unsigned a0, unsigned a1, unsigned a2, unsigned a3,
                                         unsigned b0, unsigned b1) {
    asm("mma.sync.aligned.m16n8k8.row.col.f32.tf32.tf32.f32 "
        "{%0,%1,%2,%3},{%4,%5,%6,%7},{%8,%9},{%0,%1,%2,%3};"
        : "+f"(d[0]), "+f"(d[1]), "+f"(d[2]), "+f"(d[3])
        : "r"(a0), "r"(a1), "r"(a2), "r"(a3), "r"(b0), "r"(b1));
}

__device__ __forceinline__ void mma_bf16_k8(float* d, unsigned a0, unsigned a1, unsigned b0) {
    asm("mma.sync.aligned.m16n8k8.row.col.f32.bf16.bf16.f32 "
        "{%0,%1,%2,%3},{%4,%5},{%6},{%0,%1,%2,%3};"
        : "+f"(d[0]), "+f"(d[1]), "+f"(d[2]), "+f"(d[3])
        : "r"(a0), "r"(a1), "r"(b0));
}
__device__ __forceinline__ void mma_bf16_k16(float* d,
                                             unsigned a0, unsigned a1, unsigned a2, unsigned a3,
                                             unsigned b0, unsigned b1) {
    asm("mma.sync.aligned.m16n8k16.row.col.f32.bf16.bf16.f32 "
        "{%0,%1,%2,%3},{%4,%5,%6,%7},{%8,%9},{%0,%1,%2,%3};"
        : "+f"(d[0]), "+f"(d[1]), "+f"(d[2]), "+f"(d[3])
        : "r"(a0), "r"(a1), "r"(a2), "r"(a3), "r"(b0), "r"(b1));
}

__device__ __forceinline__ void cp16(unsigned int saddr, const void* gaddr) {
    asm volatile("cp.async.ca.shared.global [%0], [%1], 16;" :: "r"(saddr), "l"(gaddr));
}
__device__ __forceinline__ void cp_commit() {
    asm volatile("cp.async.commit_group;" ::: "memory");
}
__device__ __forceinline__ void cp_wait0() {
    asm volatile("cp.async.wait_group 0;" ::: "memory");
}

// ---------------------------------------------------------------------------
// Kernel 0: pack weights. Conv weights -> duplicated bf16x2 hi/lo pairs in
// fragment order. Projection weights -> fp32 fragment order (as before).
// frag off = ((grp*8 + ntg)*32 + lane)*2 + e ; j = tq + 4e ; k = grp*8 + j
// ---------------------------------------------------------------------------
__global__ void k0_pack(const float* __restrict__ wA, const float* __restrict__ wB,
                        const float* __restrict__ wq, const float* __restrict__ wk,
                        const float* __restrict__ wv)
{
    int t = blockIdx.x * 256 + threadIdx.x;
    if (t < 12288) {
        int g = t >> 9, r = t & 511;
        int ntg = r >> 6, q = r & 63;
        int lane = q >> 1, e = q & 1;
        int gid = lane >> 2, tq = lane & 3;
        int n = ntg * 8 + gid;
        int k = g * 8 + tq + 4 * e;
        float a = wA[n * 192 + k], bw = wB[n * 192 + k];
        float ah = __bfloat162float(__float2bfloat16(a));
        float bh = __bfloat162float(__float2bfloat16(bw));
        float al = a - ah, bl = bw - bh;
        int off = ((g * 8 + ntg) * 32 + lane) * 2 + e;
        g_cwAh[off] = pack_bf16(ah, ah);
        g_cwAl[off] = pack_bf16(al, al);
        g_cwBh[off] = pack_bf16(bh, bh);
        g_cwBl[off] = pack_bf16(bl, bl);
    }
    if (t < 4096) {
        int ks = t >> 9, r = t & 511;
        int ntg = r >> 6, q = r & 63;
        int lane = q >> 1, e = q & 1;
        int gid = lane >> 2, tq = lane & 3;
        g_fwv[((ks * 8 + ntg) * 32 + lane) * 2 + e] = wv[(ntg * 8 + gid) * 64 + ks * 8 + tq + 4 * e];
    }
    if (t < 512) {
        int ks = t >> 6, q = t & 63;
        int lane = q >> 1, e = q & 1;
        int gid = lane >> 2, tq = lane & 3;
        int k = ks * 8 + tq + 4 * e;
        g_fwq[(ks * 32 + lane) * 2 + e] = wq[gid * 64 + k] * LOG2E;
        g_fwk[(ks * 32 + lane) * 2 + e] = wk[gid * 64 + k];
    }
}

// ---------------------------------------------------------------------------
// Kernel 1: conv(x2) via split-bf16 k16 mma (hi+lo, duplicated weights)
// + GLU gate + v/q/k projections (tf32 mma).
// grid (QT, B): 48-row tiles, 192 threads (6 warps: mw=wid>>1, nw=wid&1)
// smem: xs[48][196] packed bf16x2 + hs[48][68] fp32 = 12672 words (~50.7KB)
// ---------------------------------------------------------------------------
__global__ void __launch_bounds__(192, 3)
k1_conv_qkv(const float* __restrict__ X,
            const float* __restrict__ bA, const float* __restrict__ bB,
            const float* __restrict__ bq, const float* __restrict__ bk,
            const float* __restrict__ bv)
{
    extern __shared__ float sm1[];
    unsigned* xs = (unsigned*)sm1;   // [l][pitch 196] packed (xh,xl) bf16x2
    float* hs = sm1 + 9408;          // [l][pitch 68]

    const int tid  = threadIdx.x;
    const int wid  = tid >> 5;
    const int lane = tid & 31;
    const int gid  = lane >> 2;
    const int tq   = lane & 3;
    const int mw   = wid >> 1;
    const int nw   = wid & 1;
    const int m0   = mw * 16;
    const int nbase = nw * 32;
    const int b    = blockIdx.y;
    const int l0   = blockIdx.x * 48;

    // ---- stage conv taps xs[l][k] = packed (bf16 hi, bf16 lo) ----
    for (int e = tid; e < 48 * 192; e += 192) {
        int l = e / 192, r = e - l * 192;
        int ci = r / 3, k = r - ci * 3;
        int gl = l0 + l;
        float v = 0.f;
        if (gl < L_) {
            int n = gl / 12, t = gl - n * 12;
            int tt = t - 2 + k;
            if (tt >= 0) v = X[((b * N_ + n) * T_ + tt) * C_ + ci];
        }
        float vh = __bfloat162float(__float2bfloat16(v));
        xs[l * 196 + r] = pack_bf16(vh, v - vh);
    }
    __syncthreads();

    // ---- conv GEMMs: split-bf16 k16, 4 mma per (group, ntile) ----
    float accA[4][4], accB[4][4];
    #pragma unroll
    for (int i = 0; i < 4; i++)
        #pragma unroll
        for (int j = 0; j < 4; j++) { accA[i][j] = 0.f; accB[i][j] = 0.f; }

    #pragma unroll 4
    for (int g = 0; g < 24; g++) {
        const int k0 = g * 8;
        unsigned a0 = xs[(m0 + gid) * 196 + k0 + tq];
        unsigned a1 = xs[(m0 + gid + 8) * 196 + k0 + tq];
        unsigned a2 = xs[(m0 + gid) * 196 + k0 + tq + 4];
        unsigned a3 = xs[(m0 + gid + 8) * 196 + k0 + tq + 4];
        #pragma unroll
        for (int nt = 0; nt < 4; nt++) {
            const int off = ((g * 8 + (nbase >> 3) + nt) * 32 + lane) * 2;
            uint2 wah = __ldg((const uint2*)&g_cwAh[off]);
            uint2 wal = __ldg((const uint2*)&g_cwAl[off]);
            uint2 wbh = __ldg((const uint2*)&g_cwBh[off]);
            uint2 wbl = __ldg((const uint2*)&g_cwBl[off]);
            mma_bf16_k16(accA[nt], a0, a1, a2, a3, wah.x, wah.y);
            mma_bf16_k16(accA[nt], a0, a1, a2, a3, wal.x, wal.y);
            mma_bf16_k16(accB[nt], a0, a1, a2, a3, wbh.x, wbh.y);
            mma_bf16_k16(accB[nt], a0, a1, a2, a3, wbl.x, wbl.y);
        }
    }

    // ---- gate: h = (A+bA)*sigmoid(B+bB); write hs + g_h ----
    {
        const int rlo = m0 + gid, rhi = rlo + 8;
        const int gl_lo = l0 + rlo, gl_hi = l0 + rhi;
        #pragma unroll
        for (int nt = 0; nt < 4; nt++) {
            const int col = nbase + nt * 8 + 2 * tq;
            float ba0 = __ldg(bA + col), ba1 = __ldg(bA + col + 1);
            float bb0 = __ldg(bB + col), bb1 = __ldg(bB + col + 1);
            float h00 = (accA[nt][0] + ba0) / (1.f + __expf(-(accB[nt][0] + bb0)));
            float h01 = (accA[nt][1] + ba1) / (1.f + __expf(-(accB[nt][1] + bb1)));
            float h10 = (accA[nt][2] + ba0) / (1.f + __expf(-(accB[nt][2] + bb0)));
            float h11 = (accA[nt][3] + ba1) / (1.f + __expf(-(accB[nt][3] + bb1)));
            *(float2*)&hs[rlo * 68 + col] = make_float2(h00, h01);
            *(float2*)&hs[rhi * 68 + col] = make_float2(h10, h11);
            if (gl_lo < L_) *(float2*)&g_h[((size_t)b * LPAD + gl_lo) * 64 + col] = make_float2(h00, h01);
            if (gl_hi < L_) *(float2*)&g_h[((size_t)b * LPAD + gl_hi) * 64 + col] = make_float2(h10, h11);
        }
    }
    __syncthreads();

    // ---- v = h @ wv^T + bv (tf32 mma), stored PAIR-PERMUTED bf16 ----
    {
        float accV[4][4];
        #pragma unroll
        for (int i = 0; i < 4; i++)
            #pragma unroll
            for (int j = 0; j < 4; j++) accV[i][j] = 0.f;

        #pragma unroll
        for (int ks = 0; ks < 8; ks++) {
            const int k0 = ks * 8;
            unsigned a0 = __float_as_uint(hs[(m0 + gid) * 68 + k0 + tq]);
            unsigned a1 = __float_as_uint(hs[(m0 + gid + 8) * 68 + k0 + tq]);
            unsigned a2 = __float_as_uint(hs[(m0 + gid) * 68 + k0 + tq + 4]);
            unsigned a3 = __float_as_uint(hs[(m0 + gid + 8) * 68 + k0 + tq + 4]);
            #pragma unroll
            for (int nt = 0; nt < 4; nt++) {
                const int off = ((ks * 8 + (nbase >> 3) + nt) * 32 + lane) * 2;
                float2 w = __ldg((const float2*)&g_fwv[off]);
                mma_tf32(accV[nt], a0, a1, a2, a3,
                         __float_as_uint(w.x), __float_as_uint(w.y));
            }
        }

        const int gb = l0 + m0;
        const int pos_lo = gb + ((gid >> 1) << 2) + (gid & 1);
        const int pos_hi = pos_lo + 2;
        #pragma unroll
        for (int nt = 0; nt < 4; nt++) {
            const int col = nbase + nt * 8 + 2 * tq;
            float bv0 = __ldg(bv + col), bv1 = __ldg(bv + col + 1);
            g_vb[((size_t)(b * 64 + col))     * LPAD + pos_lo] = __float2bfloat16(accV[nt][0] + bv0);
            g_vb[((size_t)(b * 64 + col + 1)) * LPAD + pos_lo] = __float2bfloat16(accV[nt][1] + bv1);
            g_vb[((size_t)(b * 64 + col))     * LPAD + pos_hi] = __float2bfloat16(accV[nt][2] + bv0);
            g_vb[((size_t)(b * 64 + col + 1)) * LPAD + pos_hi] = __float2bfloat16(accV[nt][3] + bv1);
        }
    }

    // ---- q,k projections (nw==0 warps); q in log2e-scaled domain ----
    if (nw == 0) {
        float accQ[4] = {0.f, 0.f, 0.f, 0.f};
        float accK[4] = {0.f, 0.f, 0.f, 0.f};

        #pragma unroll
        for (int ks = 0; ks < 8; ks++) {
            const int k0 = ks * 8;
            unsigned a0 = __float_as_uint(hs[(m0 + gid) * 68 + k0 + tq]);
            unsigned a1 = __float_as_uint(hs[(m0 + gid + 8) * 68 + k0 + tq]);
            unsigned a2 = __float_as_uint(hs[(m0 + gid) * 68 + k0 + tq + 4]);
            unsigned a3 = __float_as_uint(hs[(m0 + gid + 8) * 68 + k0 + tq + 4]);
            float2 wqf = __ldg((const float2*)&g_fwq[(ks * 32 + lane) * 2]);
            float2 wkf = __ldg((const float2*)&g_fwk[(ks * 32 + lane) * 2]);
            mma_tf32(accQ, a0, a1, a2, a3, __float_as_uint(wqf.x), __float_as_uint(wqf.y));
            mma_tf32(accK, a0, a1, a2, a3, __float_as_uint(wkf.x), __float_as_uint(wkf.y));
        }

        const int gl_lo = l0 + m0 + gid, gl_hi = gl_lo + 8;
        float bq0 = __ldg(bq + 2 * tq) * LOG2E, bq1 = __ldg(bq + 2 * tq + 1) * LOG2E;
        float bk0 = __ldg(bk + 2 * tq), bk1 = __ldg(bk + 2 * tq + 1);
        char* qbase = (char*)g_qb + ((size_t)b * LPAD) * 16;
        char* kbase = (char*)g_kb + ((size_t)b * LPAD) * 16;
        *(unsigned*)(qbase + (size_t)gl_lo * 16 + tq * 4) = pack_bf16(accQ[0] + bq0, accQ[1] + bq1);
        *(unsigned*)(qbase + (size_t)gl_hi * 16 + tq * 4) = pack_bf16(accQ[2] + bq0, accQ[3] + bq1);
        *(unsigned*)(kbase + (size_t)gl_lo * 16 + tq * 4) = pack_bf16(accK[0] + bk0, accK[1] + bk1);
        *(unsigned*)(kbase + (size_t)gl_hi * 16 + tq * 4) = pack_bf16(accK[2] + bk0, accK[3] + bk1);
    }
}

// ---------------------------------------------------------------------------
// Kernel 2: flash attention, 128-key mega-tiles, log2-domain softmax,
// bf16 mma, P in registers, ones-channel denominator. oS aliases vS0.
// smem words: vS0[72*72] | vS1 | kS[2][128*4] | mxS[2*48] | ssS[2*48]
// total 11584 (~46.3KB, 4 blocks/SM)
// ---------------------------------------------------------------------------
__global__ void __launch_bounds__(192, 4)
k2_attn(const float* __restrict__ gamma, float* __restrict__ out)
{
    extern __shared__ float sm[];
    float* vS0 = sm;                  // [72 ch][72 words], data words 0..63
    float* vS1 = sm + 5184;
    float* kS0 = sm + 10368;          // 128 keys x 16B
    float* kS1 = sm + 10880;
    float* mxS = sm + 11392;          // [nw][48]
    float* ssS = sm + 11488;          // [nw][48]
    float* oS  = sm;                  // [48][66] ALIASES vS0 (post-loop only)

    const int tid  = threadIdx.x;
    const int wid  = tid >> 5;
    const int lane = tid & 31;
    const int gid  = lane >> 2;
    const int tq   = lane & 3;
    const int mw   = wid >> 1;        // 0..2
    const int nw   = wid & 1;         // 0..1
    const int m0   = mw * 16;
    const int kb   = nw * 32;
    const int b    = blockIdx.y;
    const int l0   = blockIdx.x * 48;

    const float* kS[2] = {kS0, kS1};
    const float* vS[2] = {vS0, vS1};

    unsigned kBase[2], vBase[2];
    kBase[0] = (unsigned)__cvta_generic_to_shared(kS0);
    kBase[1] = (unsigned)__cvta_generic_to_shared(kS1);
    vBase[0] = (unsigned)__cvta_generic_to_shared(vS0);
    vBase[1] = (unsigned)__cvta_generic_to_shared(vS1);

    // ---- init constant rows 64..71 of both v buffers (row 64 = bf16 ones) ----
    for (int e = tid; e < 1152; e += 192) {
        int bufi = e / 576, r = (e % 576) / 72, w = e % 72;
        float* dst = (bufi ? vS1 : vS0) + (64 + r) * 72 + w;
        *(unsigned*)dst = (r == 0) ? 0x3F803F80u : 0u;
    }

    // ---- prologue: tile 0 (128 keys) -> buf 0 ----
    {
        const char* kg = (const char*)g_kb + ((size_t)b * LPAD) * 16;
        if (tid < 128) cp16(kBase[0] + tid * 16, kg + tid * 16);
        const char* vg = (const char*)g_vb + ((size_t)b * 64 * LPAD) * 2;
        #pragma unroll
        for (int u = 0; u < 6; u++) {
            int e = tid + u * 192;
            if (e < 1024) {
                int row = e >> 4, cc = e & 15;
                cp16(vBase[0] + row * 288 + cc * 16, vg + (size_t)row * (LPAD * 2) + cc * 16);
            }
        }
        cp_commit();
    }

    unsigned qa0, qa1;
    {
        const char* qrow = (const char*)g_qb + ((size_t)b * LPAD + l0 + m0) * 16;
        qa0 = *(const unsigned*)(qrow + gid * 16 + 4 * tq);
        qa1 = *(const unsigned*)(qrow + (gid + 8) * 16 + 4 * tq);
    }

    float acc[9][4];                  // tiles 0..7 = channels, tile 8 = denominator
    #pragma unroll
    for (int i = 0; i < 9; i++)
        #pragma unroll
        for (int j = 0; j < 4; j++) acc[i][j] = 0.f;

    float mxlo = -1e30f, mxhi = -1e30f;

    int buf = 0;
    for (int it = 0; it < NT2; it++, buf ^= 1) {
        cp_wait0();
        __syncthreads();

        const char* kC = (const char*)kS[buf];
        const char* vC = (const char*)vS[buf];

        #pragma unroll
        for (int h = 0; h < 2; h++) {
            const int mvalid = L_ - it * 128 - h * 64;

            // ---- QK^T for this half ----
            float s[4][4];
            #pragma unroll
            for (int nt = 0; nt < 4; nt++) {
                s[nt][0] = s[nt][1] = s[nt][2] = s[nt][3] = 0.f;
                unsigned bb = *(const unsigned*)(kC + (h * 64 + kb + nt * 8 + gid) * 16 + 4 * tq);
                mma_bf16_k8(s[nt], qa0, qa1, bb);
            }

            // ---- prefetch next mega-tile (once, from half 0) ----
            if (h == 0 && it + 1 < NT2) {
                const size_t mnext = (size_t)(it + 1) * 128;
                const char* kg = (const char*)g_kb + ((size_t)b * LPAD + mnext) * 16;
                const char* vg = (const char*)g_vb + ((size_t)b * 64 * LPAD + mnext) * 2;
                int nb = buf ^ 1;
                if (tid < 128) cp16(kBase[nb] + tid * 16, kg + tid * 16);
                #pragma unroll
                for (int u = 0; u < 6; u++) {
                    int e = tid + u * 192;
                    if (e < 1024) {
                        int row = e >> 4, cc = e & 15;
                        cp16(vBase[nb] + row * 288 + cc * 16, vg + (size_t)row * (LPAD * 2) + cc * 16);
                    }
                }
                cp_commit();
            }

            // ---- mask ----
            if (mvalid < 64) {
                #pragma unroll
                for (int nt = 0; nt < 4; nt++) {
                    int c0 = kb + nt * 8 + 2 * tq;
                    if (c0 >= mvalid)     { s[nt][0] = -1e30f; s[nt][2] = -1e30f; }
                    if (c0 + 1 >= mvalid) { s[nt][1] = -1e30f; s[nt][3] = -1e30f; }
                }
            }

            // ---- warp-local row max / rescale (log2 domain) ----
            float rlo = fmaxf(fmaxf(s[0][0], s[0][1]), fmaxf(s[1][0], s[1][1]));
            rlo = fmaxf(rlo, fmaxf(fmaxf(s[2][0], s[2][1]), fmaxf(s[3][0], s[3][1])));
            float rhi = fmaxf(fmaxf(s[0][2], s[0][3]), fmaxf(s[1][2], s[1][3]));
            rhi = fmaxf(rhi, fmaxf(fmaxf(s[2][2], s[2][3]), fmaxf(s[3][2], s[3][3])));
            rlo = fmaxf(rlo, __shfl_xor_sync(0xffffffff, rlo, 1));
            rlo = fmaxf(rlo, __shfl_xor_sync(0xffffffff, rlo, 2));
            rhi = fmaxf(rhi, __shfl_xor_sync(0xffffffff, rhi, 1));
            rhi = fmaxf(rhi, __shfl_xor_sync(0xffffffff, rhi, 2));
            float nmxlo = fmaxf(mxlo, rlo);
            float nmxhi = fmaxf(mxhi, rhi);
            float corrlo = ex2(mxlo - nmxlo);
            float corrhi = ex2(mxhi - nmxhi);
            mxlo = nmxlo; mxhi = nmxhi;

            // ---- exp2 in place ----
            #pragma unroll
            for (int nt = 0; nt < 4; nt++) {
                s[nt][0] = ex2(s[nt][0] - mxlo);
                s[nt][1] = ex2(s[nt][1] - mxlo);
                s[nt][2] = ex2(s[nt][2] - mxhi);
                s[nt][3] = ex2(s[nt][3] - mxhi);
            }

            // ---- pack P into bf16 A-fragments ----
            unsigned pa[2][4];
            pa[0][0] = pack_bf16(s[0][0], s[0][1]);
            pa[0][1] = pack_bf16(s[0][2], s[0][3]);
            pa[0][2] = pack_bf16(s[1][0], s[1][1]);
            pa[0][3] = pack_bf16(s[1][2], s[1][3]);
            pa[1][0] = pack_bf16(s[2][0], s[2][1]);
            pa[1][1] = pack_bf16(s[2][2], s[2][3]);
            pa[1][2] = pack_bf16(s[3][0], s[3][1]);
            pa[1][3] = pack_bf16(s[3][2], s[3][3]);

            // ---- rescale accumulators (skip when no row max moved) ----
            if (!__all_sync(0xffffffffu, (corrlo == 1.f) & (corrhi == 1.f))) {
                #pragma unroll
                for (int nt = 0; nt < 9; nt++) {
                    acc[nt][0] *= corrlo; acc[nt][1] *= corrlo;
                    acc[nt][2] *= corrhi; acc[nt][3] *= corrhi;
                }
            }

            // ---- P@V (+ones channel): 2 k16 steps x 9 tiles, LDS.64 paired V ----
            #pragma unroll
            for (int ks = 0; ks < 2; ks++) {
                const int basew = h * 32 + (kb >> 1) + ks * 8;
                #pragma unroll
                for (int nt = 0; nt < 9; nt++) {
                    uint2 bb = *(const uint2*)(vC + (nt * 8 + gid) * 288 + (basew + 2 * tq) * 4);
                    mma_bf16_k16(acc[nt], pa[ks][0], pa[ks][1], pa[ks][2], pa[ks][3], bb.x, bb.y);
                }
            }
        }
    }

    // ---- split-softmax combine (log2 domain) ----
    if (tq == 0) {
        mxS[nw * 48 + m0 + gid]     = mxlo;
        mxS[nw * 48 + m0 + gid + 8] = mxhi;
        ssS[nw * 48 + m0 + gid]     = acc[8][0];
        ssS[nw * 48 + m0 + gid + 8] = acc[8][2];
    }
    __syncthreads();   // all V reads done; oS may now reuse vS0 space

    const int rlo_i = m0 + gid, rhi_i = m0 + gid + 8;
    float Mlo = fmaxf(mxS[rlo_i], mxS[48 + rlo_i]);
    float Mhi = fmaxf(mxS[rhi_i], mxS[48 + rhi_i]);
    float denlo = ssS[rlo_i] * ex2(mxS[rlo_i] - Mlo) + ssS[48 + rlo_i] * ex2(mxS[48 + rlo_i] - Mlo);
    float denhi = ssS[rhi_i] * ex2(mxS[rhi_i] - Mhi) + ssS[48 + rhi_i] * ex2(mxS[48 + rhi_i] - Mhi);
    float sclo = ex2(mxlo - Mlo) / denlo;
    float schi = ex2(mxhi - Mhi) / denhi;

    if (nw == 0) {
        #pragma unroll
        for (int nt = 0; nt < 8; nt++) {
            const int col = nt * 8 + 2 * tq;
            oS[rlo_i * 66 + col]     = acc[nt][0] * sclo;
            oS[rlo_i * 66 + col + 1] = acc[nt][1] * sclo;
            oS[rhi_i * 66 + col]     = acc[nt][2] * schi;
            oS[rhi_i * 66 + col + 1] = acc[nt][3] * schi;
        }
    }
    __syncthreads();

    if (nw == 1) {
        const float g = gamma[0];
        const int gl_lo = l0 + rlo_i;
        const int gl_hi = l0 + rhi_i;
        #pragma unroll
        for (int nt = 0; nt < 8; nt++) {
            const int col = nt * 8 + 2 * tq;
            if (gl_lo < L_) {
                float2 h2 = *(const float2*)&g_h[((size_t)b * LPAD + gl_lo) * 64 + col];
                float2 o;
                o.x = g * (oS[rlo_i * 66 + col]     + acc[nt][0] * sclo) + h2.x;
                o.y = g * (oS[rlo_i * 66 + col + 1] + acc[nt][1] * sclo) + h2.y;
                *(float2*)&out[((size_t)b * L_ + gl_lo) * 64 + col] = o;
            }
            if (gl_hi < L_) {
                float2 h2 = *(const float2*)&g_h[((size_t)b * LPAD + gl_hi) * 64 + col];
                float2 o;
                o.x = g * (oS[rhi_i * 66 + col]     + acc[nt][2] * schi) + h2.x;
                o.y = g * (oS[rhi_i * 66 + col + 1] + acc[nt][3] * schi) + h2.y;
                *(float2*)&out[((size_t)b * L_ + gl_hi) * 64 + col] = o;
            }
        }
    }
}

// ---------------------------------------------------------------------------
extern "C" void kernel_launch(void* const* d_in, const int* in_sizes, int n_in,
                              void* d_out, int out_size)
{
    const float* X     = (const float*)d_in[0];
    const float* wA    = (const float*)d_in[1];
    const float* bA    = (const float*)d_in[2];
    const float* wB    = (const float*)d_in[3];
    const float* bB    = (const float*)d_in[4];
    const float* wq    = (const float*)d_in[5];
    const float* bq    = (const float*)d_in[6];
    const float* wk    = (const float*)d_in[7];
    const float* bk    = (const float*)d_in[8];
    const float* wv    = (const float*)d_in[9];
    const float* bv    = (const float*)d_in[10];
    const float* gamma = (const float*)d_in[11];
    float* out = (float*)d_out;

    const size_t smem1 = 12672 * sizeof(float);   // ~50.7KB
    cudaFuncSetAttribute(k1_conv_qkv, cudaFuncAttributeMaxDynamicSharedMemorySize, (int)smem1);
    const size_t smem2 = 11584 * sizeof(float);   // ~46.3KB -> 4 blocks/SM
    cudaFuncSetAttribute(k2_attn, cudaFuncAttributeMaxDynamicSharedMemorySize, (int)smem2);

    dim3 grid(QT, B_);
    k0_pack<<<48, 256>>>(wA, wB, wq, wk, wv);
    k1_conv_qkv<<<grid, 192, smem1>>>(X, bA, bB, bq, bk, bv);
    k2_attn<<<grid, 192, smem2>>>(gamma, out);
}